// round 1
// baseline (speedup 1.0000x reference)
#include <cuda_runtime.h>
#include <cuda_bf16.h>

// Problem: CapsuleModel2_72499047956924
//   inputs (metadata order):
//     0: class_capsules  f32 [B,H,W,D]   (8*64*128*272 = 17,825,792)
//     1: W               f32 [D,NC]      (272*19)
//     2: b               f32 [NC]        (19)
//     3: point_idx       i32 [P]         (524288)  flat indices into [B*H*W]
//     4: segment_ids     i32 [P]         sorted, values in [0, NI)
//     (5: num_segments scalar, unused — NI derived from out_size)
//   output: f32 [NI, NC] = sigmoid(segment_mean(feats[point_idx]) @ W + b)
//
// One CTA per segment. segment_ids is sorted -> contiguous range per segment,
// found by binary search. Thread t accumulates feature dim t privately
// (coalesced 1088B row reads, no atomics). Fused linear+sigmoid epilogue.

#define BLOCK 288          // 9 warps; covers D=272 one dim/thread (supports D<=576)
#define CHUNK 288          // point-index staging chunk
#define NWARP (BLOCK / 32)

__global__ __launch_bounds__(BLOCK)
void capsule_seg_pool_kernel(const float* __restrict__ feats,   // [G, D] flattened grid
                             const float* __restrict__ Wm,      // [D, NC]
                             const float* __restrict__ bias,    // [NC]
                             const int*   __restrict__ point_idx,
                             const int*   __restrict__ segment_ids,
                             float*       __restrict__ out,     // [NI, NC]
                             int P, int D, int NC)
{
    __shared__ int   s_range[2];
    __shared__ int   s_idx[CHUNK];
    __shared__ float s_pooled[576];

    const int tid = threadIdx.x;
    const int seg = blockIdx.x;

    // --- segment boundaries: first index with segment_ids >= (seg + tid) ---
    if (tid < 2) {
        int target = seg + tid;
        int lo = 0, hi = P;
        while (lo < hi) {
            int mid = (lo + hi) >> 1;
            if (__ldg(&segment_ids[mid]) < target) lo = mid + 1;
            else                                   hi = mid;
        }
        s_range[tid] = lo;
    }
    __syncthreads();

    const int start = s_range[0];
    const int end   = s_range[1];
    const int count = end - start;

    // --- accumulate: thread t owns dims t (and t+BLOCK if D>BLOCK) ---
    const int  d0 = tid;
    const int  d1 = tid + BLOCK;
    const bool a0 = (d0 < D);
    const bool a1 = (d1 < D);
    float acc0 = 0.f, acc1 = 0.f;

    for (int base = start; base < end; base += CHUNK) {
        const int n = min(CHUNK, end - base);
        if (tid < n) s_idx[tid] = __ldg(&point_idx[base + tid]);
        __syncthreads();

        #pragma unroll 4
        for (int i = 0; i < n; ++i) {
            const float* row = feats + (size_t)s_idx[i] * (size_t)D;
            if (a0) acc0 += __ldg(&row[d0]);
            if (a1) acc1 += __ldg(&row[d1]);
        }
        __syncthreads();
    }

    const float inv = 1.0f / (float)max(count, 1);
    if (a0) s_pooled[d0] = acc0 * inv;
    if (a1) s_pooled[d1] = acc1 * inv;
    __syncthreads();

    // --- fused linear + sigmoid: warp w handles cols w, w+NWARP, ... ---
    const int warp = tid >> 5;
    const int lane = tid & 31;
    for (int c = warp; c < NC; c += NWARP) {
        float dot = 0.f;
        for (int d = lane; d < D; d += 32)
            dot += s_pooled[d] * __ldg(&Wm[(size_t)d * NC + c]);
        #pragma unroll
        for (int off = 16; off > 0; off >>= 1)
            dot += __shfl_down_sync(0xffffffffu, dot, off);
        if (lane == 0) {
            float x = dot + __ldg(&bias[c]);
            out[(size_t)seg * NC + c] = 1.0f / (1.0f + __expf(-x));
        }
    }
}

extern "C" void kernel_launch(void* const* d_in, const int* in_sizes, int n_in,
                              void* d_out, int out_size)
{
    const float* feats       = (const float*)d_in[0];
    const float* Wm          = (const float*)d_in[1];
    const float* bias        = (const float*)d_in[2];
    const int*   point_idx   = (const int*)  d_in[3];
    const int*   segment_ids = (const int*)  d_in[4];
    float*       out         = (float*)      d_out;

    const int NC = in_sizes[2];            // 19
    const int D  = in_sizes[1] / NC;       // 272
    const int P  = in_sizes[3];            // 524288
    const int NI = out_size / NC;          // 4096

    capsule_seg_pool_kernel<<<NI, BLOCK>>>(feats, Wm, bias, point_idx,
                                           segment_ids, out, P, D, NC);
}

// round 2
// speedup vs baseline: 1.4483x; 1.4483x over previous
#include <cuda_runtime.h>
#include <cuda_bf16.h>

// CapsuleModel2: gather[P,272] -> segment mean (sorted ids) -> sigmoid(linear)
// R2: vectorized gather. 68 float4 "slots" per row x 4 point "planes" = 272
// active threads; 4x point-unroll => 4 independent LDG.128 in flight/thread.

#define BLOCK   288            // 9 full warps (272 active in gather, all in epilogue)
#define PLANES  4
#define CHUNK   256
#define MAXSLOT 144            // supports D <= 576
#define NWARP   (BLOCK / 32)

__global__ __launch_bounds__(BLOCK)
void capsule_seg_pool_kernel(const float4* __restrict__ feats4,  // [G, D/4]
                             const float*  __restrict__ Wm,      // [D, NC]
                             const float*  __restrict__ bias,    // [NC]
                             const int*    __restrict__ point_idx,
                             const int*    __restrict__ segment_ids,
                             float*        __restrict__ out,     // [NI, NC]
                             int P, int D, int NC)
{
    __shared__ int    s_range[2];
    __shared__ int    s_idx[CHUNK];
    __shared__ float4 s_acc[PLANES * MAXSLOT];
    __shared__ float  s_pooled[4 * MAXSLOT];

    const int tid   = threadIdx.x;
    const int seg   = blockIdx.x;
    const int SLOTS = D >> 2;                  // 68 for D=272

    // --- segment boundaries (sorted segment_ids): lower_bound(seg), lower_bound(seg+1)
    if (tid < 2) {
        int target = seg + tid;
        int lo = 0, hi = P;
        while (lo < hi) {
            int mid = (lo + hi) >> 1;
            if (__ldg(&segment_ids[mid]) < target) lo = mid + 1;
            else                                   hi = mid;
        }
        s_range[tid] = lo;
    }
    __syncthreads();

    const int start = s_range[0];
    const int end   = s_range[1];
    const int count = end - start;

    const bool active = (tid < SLOTS * PLANES);
    const int  slot   = active ? (tid % SLOTS) : 0;
    const int  plane  = active ? (tid / SLOTS) : 0;

    float4 acc = make_float4(0.f, 0.f, 0.f, 0.f);

    for (int base = start; base < end; base += CHUNK) {
        const int n = min(CHUNK, end - base);
        for (int j = tid; j < n; j += BLOCK)
            s_idx[j] = __ldg(&point_idx[base + j]);
        __syncthreads();

        if (active) {
            int i = plane;
            const int nmain = n - 3 * PLANES;
            for (; i < nmain; i += 4 * PLANES) {
                const int r0 = s_idx[i];
                const int r1 = s_idx[i +     PLANES];
                const int r2 = s_idx[i + 2 * PLANES];
                const int r3 = s_idx[i + 3 * PLANES];
                float4 v0 = __ldg(feats4 + (size_t)r0 * SLOTS + slot);
                float4 v1 = __ldg(feats4 + (size_t)r1 * SLOTS + slot);
                float4 v2 = __ldg(feats4 + (size_t)r2 * SLOTS + slot);
                float4 v3 = __ldg(feats4 + (size_t)r3 * SLOTS + slot);
                acc.x += (v0.x + v1.x) + (v2.x + v3.x);
                acc.y += (v0.y + v1.y) + (v2.y + v3.y);
                acc.z += (v0.z + v1.z) + (v2.z + v3.z);
                acc.w += (v0.w + v1.w) + (v2.w + v3.w);
            }
            for (; i < n; i += PLANES) {
                float4 v = __ldg(feats4 + (size_t)s_idx[i] * SLOTS + slot);
                acc.x += v.x; acc.y += v.y; acc.z += v.z; acc.w += v.w;
            }
        }
        __syncthreads();
    }

    // --- fold the 4 planes, apply mean, stage pooled vector ---
    if (active) s_acc[plane * SLOTS + slot] = acc;
    __syncthreads();

    if (tid < SLOTS) {
        float4 a = s_acc[tid];
        float4 b = s_acc[SLOTS + tid];
        float4 c = s_acc[2 * SLOTS + tid];
        float4 d = s_acc[3 * SLOTS + tid];
        const float inv = 1.0f / (float)max(count, 1);
        s_pooled[4 * tid + 0] = ((a.x + b.x) + (c.x + d.x)) * inv;
        s_pooled[4 * tid + 1] = ((a.y + b.y) + (c.y + d.y)) * inv;
        s_pooled[4 * tid + 2] = ((a.z + b.z) + (c.z + d.z)) * inv;
        s_pooled[4 * tid + 3] = ((a.w + b.w) + (c.w + d.w)) * inv;
    }
    __syncthreads();

    // --- fused linear + sigmoid: warp w -> cols w, w+NWARP, ... ---
    const int warp = tid >> 5;
    const int lane = tid & 31;
    for (int c = warp; c < NC; c += NWARP) {
        float dot = 0.f;
        for (int d = lane; d < D; d += 32)
            dot += s_pooled[d] * __ldg(&Wm[(size_t)d * NC + c]);
        #pragma unroll
        for (int off = 16; off > 0; off >>= 1)
            dot += __shfl_down_sync(0xffffffffu, dot, off);
        if (lane == 0) {
            float x = dot + __ldg(&bias[c]);
            out[(size_t)seg * NC + c] = 1.0f / (1.0f + __expf(-x));
        }
    }
}

extern "C" void kernel_launch(void* const* d_in, const int* in_sizes, int n_in,
                              void* d_out, int out_size)
{
    const float4* feats4      = (const float4*)d_in[0];
    const float*  Wm          = (const float*) d_in[1];
    const float*  bias        = (const float*) d_in[2];
    const int*    point_idx   = (const int*)   d_in[3];
    const int*    segment_ids = (const int*)   d_in[4];
    float*        out         = (float*)       d_out;

    const int NC = in_sizes[2];            // 19
    const int D  = in_sizes[1] / NC;       // 272
    const int P  = in_sizes[3];            // 524288
    const int NI = out_size / NC;          // 4096

    capsule_seg_pool_kernel<<<NI, BLOCK>>>(feats4, Wm, bias, point_idx,
                                           segment_ids, out, P, D, NC);
}

// round 4
// speedup vs baseline: 1.5824x; 1.0925x over previous
#include <cuda_runtime.h>
#include <cuda_bf16.h>

// CapsuleModel2: gather[P,272] -> segment mean (sorted ids) -> sigmoid(linear)
// R3 (resubmit; prior run hit infra container failure): 8x point unroll
// (8 independent LDG.128 in flight per thread), 5 CTAs/SM pinned via launch
// bounds, warp-cooperative 32-ary bound search.

#define BLOCK   288            // 9 warps; 272 active in gather (68 slots x 4 planes)
#define PLANES  4
#define CHUNK   256
#define MAXSLOT 72             // supports D <= 288
#define NWARP   (BLOCK / 32)

__global__ __launch_bounds__(BLOCK, 5)
void capsule_seg_pool_kernel(const float4* __restrict__ feats4,  // [G, D/4]
                             const float*  __restrict__ Wm,      // [D, NC]
                             const float*  __restrict__ bias,    // [NC]
                             const int*    __restrict__ point_idx,
                             const int*    __restrict__ segment_ids,
                             float*        __restrict__ out,     // [NI, NC]
                             int P, int D, int NC)
{
    __shared__ int    s_range[2];
    __shared__ int    s_idx[CHUNK];
    __shared__ float4 s_acc[PLANES * MAXSLOT];
    __shared__ float  s_pooled[4 * MAXSLOT];

    const int tid   = threadIdx.x;
    const int lane  = tid & 31;
    const int wid   = tid >> 5;
    const int seg   = blockIdx.x;
    const int SLOTS = D >> 2;                  // 68 for D=272

    // --- warp-cooperative lower_bound: warp w finds first idx with ids >= seg+w
    if (wid < 2) {
        const int target = seg + wid;
        int lo = 0, hi = P;
        while (hi - lo > 32) {
            const int step = ((hi - lo) + 31) >> 5;
            int m = lo + lane * step;
            m = min(m, hi - 1);
            const bool lt = (__ldg(&segment_ids[m]) < target);
            const unsigned bal = __ballot_sync(0xffffffffu, lt);
            const int k = __popc(bal);         // probes are monotone: lanes 0..k-1 true
            int nlo = (k == 0)  ? lo : min(lo + (k - 1) * step + 1, hi);
            int nhi = (k == 32) ? hi : min(lo + k * step, hi);
            lo = nlo; hi = nhi;
        }
        {
            const int m = lo + lane;
            const bool lt = (m < hi) ? (__ldg(&segment_ids[m]) < target) : false;
            lo += __popc(__ballot_sync(0xffffffffu, lt));
        }
        if (lane == 0) s_range[wid] = lo;
    }
    __syncthreads();

    const int start = s_range[0];
    const int end   = s_range[1];
    const int count = end - start;

    const bool active = (tid < SLOTS * PLANES);
    const int  slot   = active ? (tid % SLOTS) : 0;
    const int  plane  = active ? (tid / SLOTS) : 0;

    float4 acc = make_float4(0.f, 0.f, 0.f, 0.f);

    for (int base = start; base < end; base += CHUNK) {
        const int n = min(CHUNK, end - base);
        for (int j = tid; j < n; j += BLOCK)
            s_idx[j] = __ldg(&point_idx[base + j]);
        __syncthreads();

        if (active) {
            int i = plane;
            const int nmain = n - 7 * PLANES;
            for (; i < nmain; i += 8 * PLANES) {
                const int r0 = s_idx[i];
                const int r1 = s_idx[i +     PLANES];
                const int r2 = s_idx[i + 2 * PLANES];
                const int r3 = s_idx[i + 3 * PLANES];
                const int r4 = s_idx[i + 4 * PLANES];
                const int r5 = s_idx[i + 5 * PLANES];
                const int r6 = s_idx[i + 6 * PLANES];
                const int r7 = s_idx[i + 7 * PLANES];
                float4 v0 = __ldg(feats4 + (size_t)r0 * SLOTS + slot);
                float4 v1 = __ldg(feats4 + (size_t)r1 * SLOTS + slot);
                float4 v2 = __ldg(feats4 + (size_t)r2 * SLOTS + slot);
                float4 v3 = __ldg(feats4 + (size_t)r3 * SLOTS + slot);
                float4 v4 = __ldg(feats4 + (size_t)r4 * SLOTS + slot);
                float4 v5 = __ldg(feats4 + (size_t)r5 * SLOTS + slot);
                float4 v6 = __ldg(feats4 + (size_t)r6 * SLOTS + slot);
                float4 v7 = __ldg(feats4 + (size_t)r7 * SLOTS + slot);
                acc.x += ((v0.x + v1.x) + (v2.x + v3.x)) + ((v4.x + v5.x) + (v6.x + v7.x));
                acc.y += ((v0.y + v1.y) + (v2.y + v3.y)) + ((v4.y + v5.y) + (v6.y + v7.y));
                acc.z += ((v0.z + v1.z) + (v2.z + v3.z)) + ((v4.z + v5.z) + (v6.z + v7.z));
                acc.w += ((v0.w + v1.w) + (v2.w + v3.w)) + ((v4.w + v5.w) + (v6.w + v7.w));
            }
            for (; i < n; i += PLANES) {
                float4 v = __ldg(feats4 + (size_t)s_idx[i] * SLOTS + slot);
                acc.x += v.x; acc.y += v.y; acc.z += v.z; acc.w += v.w;
            }
        }
        __syncthreads();
    }

    // --- fold planes, apply mean ---
    if (active) s_acc[plane * SLOTS + slot] = acc;
    __syncthreads();

    if (tid < SLOTS) {
        float4 a = s_acc[tid];
        float4 b = s_acc[SLOTS + tid];
        float4 c = s_acc[2 * SLOTS + tid];
        float4 d = s_acc[3 * SLOTS + tid];
        const float inv = 1.0f / (float)max(count, 1);
        s_pooled[4 * tid + 0] = ((a.x + b.x) + (c.x + d.x)) * inv;
        s_pooled[4 * tid + 1] = ((a.y + b.y) + (c.y + d.y)) * inv;
        s_pooled[4 * tid + 2] = ((a.z + b.z) + (c.z + d.z)) * inv;
        s_pooled[4 * tid + 3] = ((a.w + b.w) + (c.w + d.w)) * inv;
    }
    __syncthreads();

    // --- fused linear + sigmoid: warp w -> cols w, w+NWARP, ... ---
    for (int c = wid; c < NC; c += NWARP) {
        float dot = 0.f;
        for (int d = lane; d < D; d += 32)
            dot += s_pooled[d] * __ldg(&Wm[(size_t)d * NC + c]);
        #pragma unroll
        for (int off = 16; off > 0; off >>= 1)
            dot += __shfl_down_sync(0xffffffffu, dot, off);
        if (lane == 0) {
            float x = dot + __ldg(&bias[c]);
            out[(size_t)seg * NC + c] = 1.0f / (1.0f + __expf(-x));
        }
    }
}

extern "C" void kernel_launch(void* const* d_in, const int* in_sizes, int n_in,
                              void* d_out, int out_size)
{
    const float4* feats4      = (const float4*)d_in[0];
    const float*  Wm          = (const float*) d_in[1];
    const float*  bias        = (const float*) d_in[2];
    const int*    point_idx   = (const int*)   d_in[3];
    const int*    segment_ids = (const int*)   d_in[4];
    float*        out         = (float*)       d_out;

    const int NC = in_sizes[2];            // 19
    const int D  = in_sizes[1] / NC;       // 272
    const int P  = in_sizes[3];            // 524288
    const int NI = out_size / NC;          // 4096

    capsule_seg_pool_kernel<<<NI, BLOCK>>>(feats4, Wm, bias, point_idx,
                                           segment_ids, out, P, D, NC);
}

// round 5
// speedup vs baseline: 1.6404x; 1.0367x over previous
#include <cuda_runtime.h>
#include <cuda_bf16.h>

// CapsuleModel2: gather[P,272] -> segment mean (sorted ids) -> sigmoid(linear)
// R5: persistent single-wave grid (760 CTAs = 152 SM x 5). Each CTA owns a
// contiguous block of ~6 segments; all segment boundaries found in parallel
// (one warp per boundary). Inner loop: 8x unrolled LDG.128 gather (unchanged).

#define BLOCK   288            // 9 warps; 272 active in gather (68 slots x 4 planes)
#define PLANES  4
#define CHUNK   256
#define MAXSLOT 72             // supports D <= 288
#define NWARP   (BLOCK / 32)
#define MAXSEG  16             // max segments per CTA (+1 boundary)

__global__ __launch_bounds__(BLOCK, 5)
void capsule_seg_pool_kernel(const float4* __restrict__ feats4,  // [G, D/4]
                             const float*  __restrict__ Wm,      // [D, NC]
                             const float*  __restrict__ bias,    // [NC]
                             const int*    __restrict__ point_idx,
                             const int*    __restrict__ segment_ids,
                             float*        __restrict__ out,     // [NI, NC]
                             int P, int D, int NC, int NI, int G)
{
    __shared__ int    s_bound[MAXSEG + 1];
    __shared__ int    s_idx[CHUNK];
    __shared__ float4 s_acc[PLANES * MAXSLOT];
    __shared__ float  s_pooled[4 * MAXSLOT];

    const int tid   = threadIdx.x;
    const int lane  = tid & 31;
    const int wid   = tid >> 5;
    const int SLOTS = D >> 2;                  // 68 for D=272

    // --- this CTA's contiguous segment block (balanced split) ---
    const int lo_seg = (int)(((long long)blockIdx.x)     * NI / G);
    const int hi_seg = (int)(((long long)blockIdx.x + 1) * NI / G);
    const int nseg   = hi_seg - lo_seg;
    if (nseg <= 0) return;

    // --- all boundaries in parallel: warp w searches lower_bound(lo_seg + w) ---
    for (int t = wid; t <= nseg; t += NWARP) {
        const int target = lo_seg + t;
        int lo = 0, hi = P;
        while (hi - lo > 32) {
            const int step = ((hi - lo) + 31) >> 5;
            int m = lo + lane * step;
            m = min(m, hi - 1);
            const bool lt = (__ldg(&segment_ids[m]) < target);
            const unsigned bal = __ballot_sync(0xffffffffu, lt);
            const int k = __popc(bal);         // monotone probes: lanes 0..k-1 true
            int nlo = (k == 0)  ? lo : min(lo + (k - 1) * step + 1, hi);
            int nhi = (k == 32) ? hi : min(lo + k * step, hi);
            lo = nlo; hi = nhi;
        }
        {
            const int m = lo + lane;
            const bool lt = (m < hi) ? (__ldg(&segment_ids[m]) < target) : false;
            lo += __popc(__ballot_sync(0xffffffffu, lt));
        }
        if (lane == 0) s_bound[t] = lo;
    }
    __syncthreads();

    const bool active = (tid < SLOTS * PLANES);
    const int  slot   = active ? (tid % SLOTS) : 0;
    const int  plane  = active ? (tid / SLOTS) : 0;

    for (int s = 0; s < nseg; ++s) {
        const int seg   = lo_seg + s;
        const int start = s_bound[s];
        const int end   = s_bound[s + 1];
        const int count = end - start;

        float4 acc = make_float4(0.f, 0.f, 0.f, 0.f);

        for (int base = start; base < end; base += CHUNK) {
            const int n = min(CHUNK, end - base);
            for (int j = tid; j < n; j += BLOCK)
                s_idx[j] = __ldg(&point_idx[base + j]);
            __syncthreads();

            if (active) {
                int i = plane;
                const int nmain = n - 7 * PLANES;
                for (; i < nmain; i += 8 * PLANES) {
                    const int r0 = s_idx[i];
                    const int r1 = s_idx[i +     PLANES];
                    const int r2 = s_idx[i + 2 * PLANES];
                    const int r3 = s_idx[i + 3 * PLANES];
                    const int r4 = s_idx[i + 4 * PLANES];
                    const int r5 = s_idx[i + 5 * PLANES];
                    const int r6 = s_idx[i + 6 * PLANES];
                    const int r7 = s_idx[i + 7 * PLANES];
                    float4 v0 = __ldg(feats4 + (size_t)r0 * SLOTS + slot);
                    float4 v1 = __ldg(feats4 + (size_t)r1 * SLOTS + slot);
                    float4 v2 = __ldg(feats4 + (size_t)r2 * SLOTS + slot);
                    float4 v3 = __ldg(feats4 + (size_t)r3 * SLOTS + slot);
                    float4 v4 = __ldg(feats4 + (size_t)r4 * SLOTS + slot);
                    float4 v5 = __ldg(feats4 + (size_t)r5 * SLOTS + slot);
                    float4 v6 = __ldg(feats4 + (size_t)r6 * SLOTS + slot);
                    float4 v7 = __ldg(feats4 + (size_t)r7 * SLOTS + slot);
                    acc.x += ((v0.x + v1.x) + (v2.x + v3.x)) + ((v4.x + v5.x) + (v6.x + v7.x));
                    acc.y += ((v0.y + v1.y) + (v2.y + v3.y)) + ((v4.y + v5.y) + (v6.y + v7.y));
                    acc.z += ((v0.z + v1.z) + (v2.z + v3.z)) + ((v4.z + v5.z) + (v6.z + v7.z));
                    acc.w += ((v0.w + v1.w) + (v2.w + v3.w)) + ((v4.w + v5.w) + (v6.w + v7.w));
                }
                for (; i < n; i += PLANES) {
                    float4 v = __ldg(feats4 + (size_t)s_idx[i] * SLOTS + slot);
                    acc.x += v.x; acc.y += v.y; acc.z += v.z; acc.w += v.w;
                }
            }
            __syncthreads();
        }

        // --- fold planes, apply mean ---
        if (active) s_acc[plane * SLOTS + slot] = acc;
        __syncthreads();

        if (tid < SLOTS) {
            float4 a = s_acc[tid];
            float4 b = s_acc[SLOTS + tid];
            float4 c = s_acc[2 * SLOTS + tid];
            float4 d = s_acc[3 * SLOTS + tid];
            const float inv = 1.0f / (float)max(count, 1);
            s_pooled[4 * tid + 0] = ((a.x + b.x) + (c.x + d.x)) * inv;
            s_pooled[4 * tid + 1] = ((a.y + b.y) + (c.y + d.y)) * inv;
            s_pooled[4 * tid + 2] = ((a.z + b.z) + (c.z + d.z)) * inv;
            s_pooled[4 * tid + 3] = ((a.w + b.w) + (c.w + d.w)) * inv;
        }
        __syncthreads();

        // --- fused linear + sigmoid: warp w -> cols w, w+NWARP, ... ---
        for (int c = wid; c < NC; c += NWARP) {
            float dot = 0.f;
            for (int d = lane; d < D; d += 32)
                dot += s_pooled[d] * __ldg(&Wm[(size_t)d * NC + c]);
            #pragma unroll
            for (int off = 16; off > 0; off >>= 1)
                dot += __shfl_down_sync(0xffffffffu, dot, off);
            if (lane == 0) {
                float x = dot + __ldg(&bias[c]);
                out[(size_t)seg * NC + c] = 1.0f / (1.0f + __expf(-x));
            }
        }
        __syncthreads();
    }
}

extern "C" void kernel_launch(void* const* d_in, const int* in_sizes, int n_in,
                              void* d_out, int out_size)
{
    const float4* feats4      = (const float4*)d_in[0];
    const float*  Wm          = (const float*) d_in[1];
    const float*  bias        = (const float*) d_in[2];
    const int*    point_idx   = (const int*)   d_in[3];
    const int*    segment_ids = (const int*)   d_in[4];
    float*        out         = (float*)       d_out;

    const int NC = in_sizes[2];            // 19
    const int D  = in_sizes[1] / NC;       // 272
    const int P  = in_sizes[3];            // 524288
    const int NI = out_size / NC;          // 4096

    int G = 152 * 5;                       // one full wave on GB300 (152 SMs x 5 CTAs)
    if (G > NI) G = NI;
    // ensure per-CTA segment count fits the boundary array
    while ((NI + G - 1) / G > MAXSEG - 1) G *= 2;

    capsule_seg_pool_kernel<<<G, BLOCK>>>(feats4, Wm, bias, point_idx,
                                          segment_ids, out, P, D, NC, NI, G);
}